// round 2
// baseline (speedup 1.0000x reference)
#include <cuda_runtime.h>
#include <math.h>

#define FEAT 256
#define NQKV 768
#define NTOT 12288

// 36 MB scratch for qkv = s@W + b   (device global array: allocation-guard safe)
__device__ float g_qkv[NTOT * NQKV];

__constant__ int c_n_g[8]   = {2048, 1536, 1024, 2048, 512, 1792, 1280, 2048};
__constant__ int c_off_g[8] = {0, 2048, 3584, 4608, 6656, 7168, 8960, 10240};

// ---------------------------------------------------------------------------
// Kernel 1: QKV GEMM  g_qkv[12288,768] = s[12288,256] @ W[256,768] + b
// 64x64 tile, 4x4 frags, 256 threads, k-chunk 16.
// ---------------------------------------------------------------------------
__global__ __launch_bounds__(256) void qkv_gemm(const float* __restrict__ S,
                                                const float* __restrict__ W,
                                                const float* __restrict__ bias) {
    __shared__ float As[16][68];   // A tile transposed: As[k][m]
    __shared__ float Bs[16][68];   // B tile: Bs[k][n]

    const int m0 = blockIdx.y * 64;
    const int n0 = blockIdx.x * 64;
    const int tid = threadIdx.x;
    const int tx = tid & 15;       // 0..15  (n direction)
    const int ty = tid >> 4;       // 0..15  (m direction)

    float acc[4][4];
#pragma unroll
    for (int i = 0; i < 4; i++)
#pragma unroll
        for (int j = 0; j < 4; j++) acc[i][j] = 0.f;

    for (int k0 = 0; k0 < FEAT; k0 += 16) {
        // load A tile (64 x 16), store transposed
        {
            const int d = tid & 15, m = tid >> 4;
#pragma unroll
            for (int p = 0; p < 4; p++)
                As[d][m + p * 16] = S[(m0 + m + p * 16) * FEAT + k0 + d];
        }
        // load B tile (16 x 64)
        {
            const int c = tid & 63, dr = tid >> 6;
#pragma unroll
            for (int p = 0; p < 4; p++)
                Bs[dr + p * 4][c] = W[(k0 + dr + p * 4) * NQKV + n0 + c];
        }
        __syncthreads();
#pragma unroll
        for (int k = 0; k < 16; k++) {
            float4 a = *(const float4*)&As[k][ty * 4];
            float4 b = *(const float4*)&Bs[k][tx * 4];
            float av[4] = {a.x, a.y, a.z, a.w};
            float bv[4] = {b.x, b.y, b.z, b.w};
#pragma unroll
            for (int i = 0; i < 4; i++)
#pragma unroll
                for (int j = 0; j < 4; j++) acc[i][j] += av[i] * bv[j];
        }
        __syncthreads();
    }

#pragma unroll
    for (int i = 0; i < 4; i++) {
        const int row = m0 + ty * 4 + i;
        const int col = n0 + tx * 4;
        float4 o;
        o.x = acc[i][0] + bias[col + 0];
        o.y = acc[i][1] + bias[col + 1];
        o.z = acc[i][2] + bias[col + 2];
        o.w = acc[i][3] + bias[col + 3];
        *(float4*)&g_qkv[row * NQKV + col] = o;
    }
}

// ---------------------------------------------------------------------------
// Kernel 2: segmented flash attention, fp32.
// BLOCK_M=64 queries, BLOCK_N=64 keys per iteration, D=256, 256 threads.
// Q tile resident in smem; K streamed (transposed) in 32-d chunks; V streamed
// in 32-key chunks. Online softmax; O in registers (4 rows x 16 cols/thread).
// ---------------------------------------------------------------------------
#define QS_STRIDE 260
#define KS_STRIDE 68
#define SS_STRIDE 68
#define VS_STRIDE 260

#define SMEM_FLOATS (64 * QS_STRIDE + 32 * KS_STRIDE + 64 * SS_STRIDE + 32 * VS_STRIDE)

__global__ __launch_bounds__(256) void attn(float* __restrict__ out) {
    extern __shared__ float sm[];
    float* Qs = sm;                         // [64][260]
    float* Ks = Qs + 64 * QS_STRIDE;        // [32][68]   Ks[d][key]
    float* Ss = Ks + 32 * KS_STRIDE;        // [64][68]
    float* Vs = Ss + 64 * SS_STRIDE;        // [32][260]  Vs[key][d]

    // map blockIdx.x -> (graph, q-tile)
    int rem = blockIdx.x;
    int g = 0;
    while (rem >= (c_n_g[g] >> 6)) { rem -= c_n_g[g] >> 6; g++; }
    const int nk   = c_n_g[g];
    const int koff = c_off_g[g];
    const int q0   = koff + rem * 64;

    const int tid = threadIdx.x;
    const int tx  = tid & 15;   // key / out-col direction
    const int ty  = tid >> 4;   // query direction

    // load Q tile (64 x 256) into smem
    const float* qkv = g_qkv;
#pragma unroll
    for (int p = 0; p < 16; p++) {
        int idx = p * 256 + tid;           // float4 index over 64x64
        int r = idx >> 6, c4 = idx & 63;
        float4 v = *(const float4*)&qkv[(q0 + r) * NQKV + c4 * 4];
        *(float4*)&Qs[r * QS_STRIDE + c4 * 4] = v;
    }
    __syncthreads();

    float O[4][16];
#pragma unroll
    for (int i = 0; i < 4; i++)
#pragma unroll
        for (int j = 0; j < 16; j++) O[i][j] = 0.f;
    float M[4] = {-INFINITY, -INFINITY, -INFINITY, -INFINITY};
    float L[4] = {0.f, 0.f, 0.f, 0.f};

    const float scale = 0.0625f;   // 1/sqrt(256)
    const int n_kt = nk >> 6;

    for (int kt = 0; kt < n_kt; kt++) {
        const int kbase = koff + kt * 64;

        // ---- S = Q @ K^T over d-chunks of 32 ----
        float acc[4][4];
#pragma unroll
        for (int i = 0; i < 4; i++)
#pragma unroll
            for (int j = 0; j < 4; j++) acc[i][j] = 0.f;

        for (int dd = 0; dd < FEAT; dd += 32) {
            // load K chunk transposed: Ks[d][key], d in [0,32), key in [0,64)
            {
                const int d = tid & 31, kb = tid >> 5;   // kb 0..7
#pragma unroll
                for (int p = 0; p < 8; p++) {
                    int key = kb + p * 8;
                    Ks[d * KS_STRIDE + key] =
                        qkv[(kbase + key) * NQKV + FEAT + dd + d];
                }
            }
            __syncthreads();
#pragma unroll 8
            for (int d = 0; d < 32; d++) {
                float a0 = Qs[(ty * 4 + 0) * QS_STRIDE + dd + d];
                float a1 = Qs[(ty * 4 + 1) * QS_STRIDE + dd + d];
                float a2 = Qs[(ty * 4 + 2) * QS_STRIDE + dd + d];
                float a3 = Qs[(ty * 4 + 3) * QS_STRIDE + dd + d];
                float4 b = *(const float4*)&Ks[d * KS_STRIDE + tx * 4];
                acc[0][0] += a0 * b.x; acc[0][1] += a0 * b.y; acc[0][2] += a0 * b.z; acc[0][3] += a0 * b.w;
                acc[1][0] += a1 * b.x; acc[1][1] += a1 * b.y; acc[1][2] += a1 * b.z; acc[1][3] += a1 * b.w;
                acc[2][0] += a2 * b.x; acc[2][1] += a2 * b.y; acc[2][2] += a2 * b.z; acc[2][3] += a2 * b.w;
                acc[3][0] += a3 * b.x; acc[3][1] += a3 * b.y; acc[3][2] += a3 * b.z; acc[3][3] += a3 * b.w;
            }
            __syncthreads();
        }

        // ---- online softmax (row groups of 16 threads share a row) ----
#pragma unroll
        for (int i = 0; i < 4; i++) {
            float s0 = acc[i][0] * scale, s1 = acc[i][1] * scale;
            float s2 = acc[i][2] * scale, s3 = acc[i][3] * scale;
            float mx = fmaxf(fmaxf(s0, s1), fmaxf(s2, s3));
#pragma unroll
            for (int off = 8; off >= 1; off >>= 1)
                mx = fmaxf(mx, __shfl_xor_sync(0xffffffffu, mx, off));
            float mnew  = fmaxf(M[i], mx);
            float alpha = __expf(M[i] - mnew);
            float p0 = __expf(s0 - mnew);
            float p1 = __expf(s1 - mnew);
            float p2 = __expf(s2 - mnew);
            float p3 = __expf(s3 - mnew);
            float4 pv = make_float4(p0, p1, p2, p3);
            *(float4*)&Ss[(ty * 4 + i) * SS_STRIDE + tx * 4] = pv;
            float rsum = p0 + p1 + p2 + p3;
#pragma unroll
            for (int off = 8; off >= 1; off >>= 1)
                rsum += __shfl_xor_sync(0xffffffffu, rsum, off);
            L[i] = L[i] * alpha + rsum;
            M[i] = mnew;
#pragma unroll
            for (int j = 0; j < 16; j++) O[i][j] *= alpha;
        }
        __syncthreads();

        // ---- O += P @ V over key-chunks of 32 ----
        for (int kk0 = 0; kk0 < 64; kk0 += 32) {
            // load V chunk: Vs[key][d], 32 keys x 256 d
#pragma unroll
            for (int p = 0; p < 8; p++) {
                int idx = p * 256 + tid;         // float4 index over 32x64
                int r = idx >> 6, c4 = idx & 63;
                float4 v = *(const float4*)&qkv[(kbase + kk0 + r) * NQKV + 2 * FEAT + c4 * 4];
                *(float4*)&Vs[r * VS_STRIDE + c4 * 4] = v;
            }
            __syncthreads();
#pragma unroll 4
            for (int kk = 0; kk < 32; kk++) {
                float a0 = Ss[(ty * 4 + 0) * SS_STRIDE + kk0 + kk];
                float a1 = Ss[(ty * 4 + 1) * SS_STRIDE + kk0 + kk];
                float a2 = Ss[(ty * 4 + 2) * SS_STRIDE + kk0 + kk];
                float a3 = Ss[(ty * 4 + 3) * SS_STRIDE + kk0 + kk];
#pragma unroll
                for (int j4 = 0; j4 < 4; j4++) {
                    float4 v = *(const float4*)&Vs[kk * VS_STRIDE + tx * 16 + j4 * 4];
                    O[0][j4 * 4 + 0] += a0 * v.x; O[0][j4 * 4 + 1] += a0 * v.y;
                    O[0][j4 * 4 + 2] += a0 * v.z; O[0][j4 * 4 + 3] += a0 * v.w;
                    O[1][j4 * 4 + 0] += a1 * v.x; O[1][j4 * 4 + 1] += a1 * v.y;
                    O[1][j4 * 4 + 2] += a1 * v.z; O[1][j4 * 4 + 3] += a1 * v.w;
                    O[2][j4 * 4 + 0] += a2 * v.x; O[2][j4 * 4 + 1] += a2 * v.y;
                    O[2][j4 * 4 + 2] += a2 * v.z; O[2][j4 * 4 + 3] += a2 * v.w;
                    O[3][j4 * 4 + 0] += a3 * v.x; O[3][j4 * 4 + 1] += a3 * v.y;
                    O[3][j4 * 4 + 2] += a3 * v.z; O[3][j4 * 4 + 3] += a3 * v.w;
                }
            }
            __syncthreads();
        }
    }

    // ---- epilogue: O / L ----
#pragma unroll
    for (int i = 0; i < 4; i++) {
        float inv = 1.0f / L[i];
        const int row = q0 + ty * 4 + i;
#pragma unroll
        for (int j4 = 0; j4 < 4; j4++) {
            float4 o;
            o.x = O[i][j4 * 4 + 0] * inv;
            o.y = O[i][j4 * 4 + 1] * inv;
            o.z = O[i][j4 * 4 + 2] * inv;
            o.w = O[i][j4 * 4 + 3] * inv;
            *(float4*)&out[row * FEAT + tx * 16 + j4 * 4] = o;
        }
    }
}

// ---------------------------------------------------------------------------
extern "C" void kernel_launch(void* const* d_in, const int* in_sizes, int n_in,
                              void* d_out, int out_size) {
    const float* s    = (const float*)d_in[0];   // [12288, 256]
    const float* W    = (const float*)d_in[1];   // [256, 768]
    const float* bias = (const float*)d_in[2];   // [768]
    float* out = (float*)d_out;                  // [12288, 256]

    const int smem_bytes = SMEM_FLOATS * (int)sizeof(float);
    cudaFuncSetAttribute(attn, cudaFuncAttributeMaxDynamicSharedMemorySize,
                         smem_bytes);

    qkv_gemm<<<dim3(NQKV / 64, NTOT / 64), 256>>>(s, W, bias);
    attn<<<192, 256, smem_bytes>>>(out);
}

// round 3
// speedup vs baseline: 1.9901x; 1.9901x over previous
#include <cuda_runtime.h>
#include <math.h>

#define FEAT 256
#define NQKV 768
#define NTOT 12288

// 36 MB scratch for qkv = s@W + b (device global array: allocation-guard safe)
__device__ float g_qkv[NTOT * NQKV];

__constant__ int c_n_g[8]   = {2048, 1536, 1024, 2048, 512, 1792, 1280, 2048};
__constant__ int c_off_g[8] = {0, 2048, 3584, 4608, 6656, 7168, 8960, 10240};

// Schedule: graphs sorted by descending key count (LPT-style launch order).
// order: g0(2048,32 tiles) g3(2048,32) g7(2048,32) g5(1792,28) g1(1536,24)
//        g6(1280,20) g2(1024,16) g4(512,8)   -> 192 tiles total
__constant__ int c_sched_g[8]     = {0, 3, 7, 5, 1, 6, 2, 4};
__constant__ int c_sched_start[8] = {0, 32, 64, 96, 124, 148, 168, 184};

// ---------------------------------------------------------------------------
// Kernel 1: QKV GEMM  g_qkv[12288,768] = s[12288,256] @ W[256,768] + b
// ---------------------------------------------------------------------------
__global__ __launch_bounds__(256) void qkv_gemm(const float* __restrict__ S,
                                                const float* __restrict__ W,
                                                const float* __restrict__ bias) {
    __shared__ float As[16][68];   // A tile transposed: As[k][m]
    __shared__ float Bs[16][68];   // B tile: Bs[k][n]

    const int m0 = blockIdx.y * 64;
    const int n0 = blockIdx.x * 64;
    const int tid = threadIdx.x;
    const int tx = tid & 15;
    const int ty = tid >> 4;

    float acc[4][4];
#pragma unroll
    for (int i = 0; i < 4; i++)
#pragma unroll
        for (int j = 0; j < 4; j++) acc[i][j] = 0.f;

    for (int k0 = 0; k0 < FEAT; k0 += 16) {
        {
            const int d = tid & 15, m = tid >> 4;
#pragma unroll
            for (int p = 0; p < 4; p++)
                As[d][m + p * 16] = S[(m0 + m + p * 16) * FEAT + k0 + d];
        }
        {
            const int c = tid & 63, dr = tid >> 6;
#pragma unroll
            for (int p = 0; p < 4; p++)
                Bs[dr + p * 4][c] = W[(k0 + dr + p * 4) * NQKV + n0 + c];
        }
        __syncthreads();
#pragma unroll
        for (int k = 0; k < 16; k++) {
            float4 a = *(const float4*)&As[k][ty * 4];
            float4 b = *(const float4*)&Bs[k][tx * 4];
            float av[4] = {a.x, a.y, a.z, a.w};
            float bv[4] = {b.x, b.y, b.z, b.w};
#pragma unroll
            for (int i = 0; i < 4; i++)
#pragma unroll
                for (int j = 0; j < 4; j++) acc[i][j] += av[i] * bv[j];
        }
        __syncthreads();
    }

#pragma unroll
    for (int i = 0; i < 4; i++) {
        const int row = m0 + ty * 4 + i;
        const int col = n0 + tx * 4;
        float4 o;
        o.x = acc[i][0] + bias[col + 0];
        o.y = acc[i][1] + bias[col + 1];
        o.z = acc[i][2] + bias[col + 2];
        o.w = acc[i][3] + bias[col + 3];
        *(float4*)&g_qkv[row * NQKV + col] = o;
    }
}

// ---------------------------------------------------------------------------
// Kernel 2: segmented flash attention, fp32, 512 threads.
// BLOCK_M=64 queries, BLOCK_N=128 keys (all graph sizes divide 128), D=256.
// Q resident in smem; K streamed transposed in 32-d chunks; V in 32-key chunks.
// Thread map: tx = tid&31 (cols), ty = tid>>5 (row groups of 4).
// ---------------------------------------------------------------------------
#define QS_STRIDE 260
#define KS_STRIDE 132
#define SS_STRIDE 132
#define VS_STRIDE 260

#define SMEM_FLOATS (64 * QS_STRIDE + 32 * KS_STRIDE + 64 * SS_STRIDE + 32 * VS_STRIDE)

__global__ __launch_bounds__(512, 1) void attn(float* __restrict__ out) {
    extern __shared__ float sm[];
    float* Qs = sm;                         // [64][260]
    float* Ks = Qs + 64 * QS_STRIDE;        // [32][132]  Ks[d][key]
    float* Ss = Ks + 32 * KS_STRIDE;        // [64][132]
    float* Vs = Ss + 64 * SS_STRIDE;        // [32][260]  Vs[key][d]

    // map blockIdx.x through descending-work schedule -> (graph, q-tile)
    int s = 0;
    while (s < 7 && blockIdx.x >= c_sched_start[s + 1]) s++;
    const int g    = c_sched_g[s];
    const int tile = blockIdx.x - c_sched_start[s];
    const int nk   = c_n_g[g];
    const int koff = c_off_g[g];
    const int q0   = koff + tile * 64;

    const int tid = threadIdx.x;
    const int tx  = tid & 31;   // 0..31  key/out-col direction
    const int ty  = tid >> 5;   // 0..15  query row group (4 rows each)

    const float* qkv = g_qkv;

    // load Q tile (64 x 256) into smem
#pragma unroll
    for (int p = 0; p < 8; p++) {
        int idx = p * 512 + tid;           // float4 index over 64x64
        int r = idx >> 6, c4 = idx & 63;
        float4 v = *(const float4*)&qkv[(q0 + r) * NQKV + c4 * 4];
        *(float4*)&Qs[r * QS_STRIDE + c4 * 4] = v;
    }
    __syncthreads();

    float O[4][8];
#pragma unroll
    for (int i = 0; i < 4; i++)
#pragma unroll
        for (int j = 0; j < 8; j++) O[i][j] = 0.f;
    float M[4] = {-INFINITY, -INFINITY, -INFINITY, -INFINITY};
    float L[4] = {0.f, 0.f, 0.f, 0.f};

    const float scale = 0.0625f;   // 1/sqrt(256)
    const int n_kt = nk >> 7;      // 128 keys per iteration

    for (int kt = 0; kt < n_kt; kt++) {
        const int kbase = koff + kt * 128;

        // ---- S = Q @ K^T over d-chunks of 32 ----
        float acc[4][4];
#pragma unroll
        for (int i = 0; i < 4; i++)
#pragma unroll
            for (int j = 0; j < 4; j++) acc[i][j] = 0.f;

        for (int dd = 0; dd < FEAT; dd += 32) {
            // load K chunk transposed: Ks[d][key], d in [0,32), key in [0,128)
            {
                const int d = tid & 31, kb = tid >> 5;   // kb 0..15
#pragma unroll
                for (int p = 0; p < 8; p++) {
                    int key = kb + p * 16;
                    Ks[d * KS_STRIDE + key] =
                        qkv[(kbase + key) * NQKV + FEAT + dd + d];
                }
            }
            __syncthreads();
#pragma unroll 8
            for (int d = 0; d < 32; d++) {
                float a0 = Qs[(ty * 4 + 0) * QS_STRIDE + dd + d];
                float a1 = Qs[(ty * 4 + 1) * QS_STRIDE + dd + d];
                float a2 = Qs[(ty * 4 + 2) * QS_STRIDE + dd + d];
                float a3 = Qs[(ty * 4 + 3) * QS_STRIDE + dd + d];
                float4 b = *(const float4*)&Ks[d * KS_STRIDE + tx * 4];
                acc[0][0] += a0 * b.x; acc[0][1] += a0 * b.y; acc[0][2] += a0 * b.z; acc[0][3] += a0 * b.w;
                acc[1][0] += a1 * b.x; acc[1][1] += a1 * b.y; acc[1][2] += a1 * b.z; acc[1][3] += a1 * b.w;
                acc[2][0] += a2 * b.x; acc[2][1] += a2 * b.y; acc[2][2] += a2 * b.z; acc[2][3] += a2 * b.w;
                acc[3][0] += a3 * b.x; acc[3][1] += a3 * b.y; acc[3][2] += a3 * b.z; acc[3][3] += a3 * b.w;
            }
            __syncthreads();
        }

        // ---- online softmax: each warp owns 4 full rows (32 lanes/row) ----
#pragma unroll
        for (int i = 0; i < 4; i++) {
            float s0 = acc[i][0] * scale, s1 = acc[i][1] * scale;
            float s2 = acc[i][2] * scale, s3 = acc[i][3] * scale;
            float mx = fmaxf(fmaxf(s0, s1), fmaxf(s2, s3));
#pragma unroll
            for (int off = 16; off >= 1; off >>= 1)
                mx = fmaxf(mx, __shfl_xor_sync(0xffffffffu, mx, off));
            float mnew  = fmaxf(M[i], mx);
            float alpha = __expf(M[i] - mnew);
            float p0 = __expf(s0 - mnew);
            float p1 = __expf(s1 - mnew);
            float p2 = __expf(s2 - mnew);
            float p3 = __expf(s3 - mnew);
            *(float4*)&Ss[(ty * 4 + i) * SS_STRIDE + tx * 4] =
                make_float4(p0, p1, p2, p3);
            float rsum = p0 + p1 + p2 + p3;
#pragma unroll
            for (int off = 16; off >= 1; off >>= 1)
                rsum += __shfl_xor_sync(0xffffffffu, rsum, off);
            L[i] = L[i] * alpha + rsum;
            M[i] = mnew;
#pragma unroll
            for (int j = 0; j < 8; j++) O[i][j] *= alpha;
        }
        __syncthreads();

        // ---- O += P @ V over key-chunks of 32 ----
        for (int kk0 = 0; kk0 < 128; kk0 += 32) {
            // load V chunk: Vs[key][d], 32 keys x 256 d
#pragma unroll
            for (int p = 0; p < 4; p++) {
                int idx = p * 512 + tid;         // float4 index over 32x64
                int r = idx >> 6, c4 = idx & 63;
                float4 v = *(const float4*)&qkv[(kbase + kk0 + r) * NQKV + 2 * FEAT + c4 * 4];
                *(float4*)&Vs[r * VS_STRIDE + c4 * 4] = v;
            }
            __syncthreads();
#pragma unroll 4
            for (int kk = 0; kk < 32; kk++) {
                float a0 = Ss[(ty * 4 + 0) * SS_STRIDE + kk0 + kk];
                float a1 = Ss[(ty * 4 + 1) * SS_STRIDE + kk0 + kk];
                float a2 = Ss[(ty * 4 + 2) * SS_STRIDE + kk0 + kk];
                float a3 = Ss[(ty * 4 + 3) * SS_STRIDE + kk0 + kk];
#pragma unroll
                for (int j4 = 0; j4 < 2; j4++) {
                    // out columns: j4*128 + tx*4 + e
                    float4 v = *(const float4*)&Vs[kk * VS_STRIDE + j4 * 128 + tx * 4];
                    O[0][j4 * 4 + 0] += a0 * v.x; O[0][j4 * 4 + 1] += a0 * v.y;
                    O[0][j4 * 4 + 2] += a0 * v.z; O[0][j4 * 4 + 3] += a0 * v.w;
                    O[1][j4 * 4 + 0] += a1 * v.x; O[1][j4 * 4 + 1] += a1 * v.y;
                    O[1][j4 * 4 + 2] += a1 * v.z; O[1][j4 * 4 + 3] += a1 * v.w;
                    O[2][j4 * 4 + 0] += a2 * v.x; O[2][j4 * 4 + 1] += a2 * v.y;
                    O[2][j4 * 4 + 2] += a2 * v.z; O[2][j4 * 4 + 3] += a2 * v.w;
                    O[3][j4 * 4 + 0] += a3 * v.x; O[3][j4 * 4 + 1] += a3 * v.y;
                    O[3][j4 * 4 + 2] += a3 * v.z; O[3][j4 * 4 + 3] += a3 * v.w;
                }
            }
            __syncthreads();
        }
    }

    // ---- epilogue: O / L ----
#pragma unroll
    for (int i = 0; i < 4; i++) {
        float inv = 1.0f / L[i];
        const int row = q0 + ty * 4 + i;
#pragma unroll
        for (int j4 = 0; j4 < 2; j4++) {
            float4 o;
            o.x = O[i][j4 * 4 + 0] * inv;
            o.y = O[i][j4 * 4 + 1] * inv;
            o.z = O[i][j4 * 4 + 2] * inv;
            o.w = O[i][j4 * 4 + 3] * inv;
            *(float4*)&out[row * FEAT + j4 * 128 + tx * 4] = o;
        }
    }
}

// ---------------------------------------------------------------------------
extern "C" void kernel_launch(void* const* d_in, const int* in_sizes, int n_in,
                              void* d_out, int out_size) {
    const float* s    = (const float*)d_in[0];   // [12288, 256]
    const float* W    = (const float*)d_in[1];   // [256, 768]
    const float* bias = (const float*)d_in[2];   // [768]
    float* out = (float*)d_out;                  // [12288, 256]

    const int smem_bytes = SMEM_FLOATS * (int)sizeof(float);
    cudaFuncSetAttribute(attn, cudaFuncAttributeMaxDynamicSharedMemorySize,
                         smem_bytes);

    qkv_gemm<<<dim3(NQKV / 64, NTOT / 64), 256>>>(s, W, bias);
    attn<<<192, 512, smem_bytes>>>(out);
}

// round 5
// speedup vs baseline: 3.7186x; 1.8686x over previous
#include <cuda_runtime.h>
#include <cuda_bf16.h>
#include <math.h>
#include <stdint.h>

#define FEAT 256
#define NQKV 768
#define NTOT 12288

// bf16 hi/lo splits produced by the GEMM epilogue (device globals: guard-safe)
__device__ __nv_bfloat16 g_qh[NTOT * FEAT];
__device__ __nv_bfloat16 g_ql[NTOT * FEAT];
__device__ __nv_bfloat16 g_kh[NTOT * FEAT];
__device__ __nv_bfloat16 g_kl[NTOT * FEAT];
__device__ __nv_bfloat16 g_vth[FEAT * NTOT];   // V transposed: [d][key]
__device__ __nv_bfloat16 g_vtl[FEAT * NTOT];

__constant__ int c_n_g[8]   = {2048, 1536, 1024, 2048, 512, 1792, 1280, 2048};
__constant__ int c_off_g[8] = {0, 2048, 3584, 4608, 6656, 7168, 8960, 10240};
// 64-row q-tiles, LPT order (desc key count): tiles {32,32,32,28,24,20,16,8}
__constant__ int c_sched_g[8]     = {0, 3, 7, 5, 1, 6, 2, 4};
__constant__ int c_sched_start[8] = {0, 32, 64, 96, 124, 148, 168, 184};

// ---------------------------------------------------------------------------
// helpers
// ---------------------------------------------------------------------------
__device__ __forceinline__ uint32_t smem_u32(const void* p) {
    uint32_t a;
    asm("{ .reg .u64 t; cvta.to.shared.u64 t, %1; cvt.u32.u64 %0, t; }"
        : "=r"(a) : "l"(p));
    return a;
}
__device__ __forceinline__ void cp16(uint32_t dst, const void* src) {
    asm volatile(
        "{ .reg .u64 g; cvta.to.global.u64 g, %1;\n\t"
        "cp.async.cg.shared.global [%0], [g], 16; }"
        ::"r"(dst), "l"(src));
}
__device__ __forceinline__ void cp_commit() {
    asm volatile("cp.async.commit_group;" ::: "memory");
}
template <int N>
__device__ __forceinline__ void cp_wait() {
    asm volatile("cp.async.wait_group %0;" ::"n"(N) : "memory");
}
__device__ __forceinline__ void hmma(float* c, uint32_t a0, uint32_t a1,
                                     uint32_t a2, uint32_t a3,
                                     uint32_t b0, uint32_t b1) {
    asm volatile(
        "mma.sync.aligned.m16n8k16.row.col.f32.bf16.bf16.f32 "
        "{%0,%1,%2,%3}, {%4,%5,%6,%7}, {%8,%9}, {%0,%1,%2,%3};"
        : "+f"(c[0]), "+f"(c[1]), "+f"(c[2]), "+f"(c[3])
        : "r"(a0), "r"(a1), "r"(a2), "r"(a3), "r"(b0), "r"(b1));
}
__device__ __forceinline__ void split2(float x, __nv_bfloat16& h, __nv_bfloat16& l) {
    h = __float2bfloat16(x);
    l = __float2bfloat16(x - __bfloat162float(h));
}
__device__ __forceinline__ uint32_t packsplit_hi(float a, float b) {
    __nv_bfloat16 ha = __float2bfloat16(a), hb = __float2bfloat16(b);
    return (uint32_t)__bfloat16_as_ushort(ha) |
           ((uint32_t)__bfloat16_as_ushort(hb) << 16);
}
__device__ __forceinline__ uint32_t packsplit_lo(float a, float b) {
    __nv_bfloat16 ha = __float2bfloat16(a), hb = __float2bfloat16(b);
    __nv_bfloat16 la = __float2bfloat16(a - __bfloat162float(ha));
    __nv_bfloat16 lb = __float2bfloat16(b - __bfloat162float(hb));
    return (uint32_t)__bfloat16_as_ushort(la) |
           ((uint32_t)__bfloat16_as_ushort(lb) << 16);
}

// ---------------------------------------------------------------------------
// Kernel 1: fp32 QKV GEMM + bf16 split epilogue
// ---------------------------------------------------------------------------
__global__ __launch_bounds__(256) void qkv_gemm(const float* __restrict__ S,
                                                const float* __restrict__ W,
                                                const float* __restrict__ bias) {
    __shared__ float As[16][68];
    __shared__ float Bs[16][68];

    const int m0 = blockIdx.y * 64;
    const int n0 = blockIdx.x * 64;
    const int tid = threadIdx.x;
    const int tx = tid & 15;
    const int ty = tid >> 4;

    float acc[4][4];
#pragma unroll
    for (int i = 0; i < 4; i++)
#pragma unroll
        for (int j = 0; j < 4; j++) acc[i][j] = 0.f;

    for (int k0 = 0; k0 < FEAT; k0 += 16) {
        {
            const int d = tid & 15, m = tid >> 4;
#pragma unroll
            for (int p = 0; p < 4; p++)
                As[d][m + p * 16] = S[(m0 + m + p * 16) * FEAT + k0 + d];
        }
        {
            const int c = tid & 63, dr = tid >> 6;
#pragma unroll
            for (int p = 0; p < 4; p++)
                Bs[dr + p * 4][c] = W[(k0 + dr + p * 4) * NQKV + n0 + c];
        }
        __syncthreads();
#pragma unroll
        for (int k = 0; k < 16; k++) {
            float4 a = *(const float4*)&As[k][ty * 4];
            float4 b = *(const float4*)&Bs[k][tx * 4];
            float av[4] = {a.x, a.y, a.z, a.w};
            float bv[4] = {b.x, b.y, b.z, b.w};
#pragma unroll
            for (int i = 0; i < 4; i++)
#pragma unroll
                for (int j = 0; j < 4; j++) acc[i][j] += av[i] * bv[j];
        }
        __syncthreads();
    }

#pragma unroll
    for (int i = 0; i < 4; i++) {
        const int row = m0 + ty * 4 + i;
        const int col = n0 + tx * 4;
        float v[4];
#pragma unroll
        for (int j = 0; j < 4; j++) v[j] = acc[i][j] + bias[col + j];

        if (n0 < 512) {
            __nv_bfloat16* Bh = (n0 < 256) ? g_qh : g_kh;
            __nv_bfloat16* Bl = (n0 < 256) ? g_ql : g_kl;
            const int cc = (n0 < 256) ? col : col - 256;
            *(uint32_t*)&Bh[row * FEAT + cc]     = packsplit_hi(v[0], v[1]);
            *(uint32_t*)&Bh[row * FEAT + cc + 2] = packsplit_hi(v[2], v[3]);
            *(uint32_t*)&Bl[row * FEAT + cc]     = packsplit_lo(v[0], v[1]);
            *(uint32_t*)&Bl[row * FEAT + cc + 2] = packsplit_lo(v[2], v[3]);
        } else {
            const int d = col - 512;
#pragma unroll
            for (int j = 0; j < 4; j++) {
                __nv_bfloat16 h, l;
                split2(v[j], h, l);
                g_vth[(d + j) * NTOT + row] = h;
                g_vtl[(d + j) * NTOT + row] = l;
            }
        }
    }
}

// ---------------------------------------------------------------------------
// Kernel 2: HMMA (mma.sync bf16 split) flash attention
// BLOCK_M=64, BLOCK_N=128, D=256, 256 threads (8 warps: 2(M) x 4(N))
// ---------------------------------------------------------------------------
// smem layout (bytes)
#define QH_OFF   0            // [64][132] u32  (Qh)     33792
#define QL_OFF   33792        // [64][132] u32  (Ql)     33792
#define S0_OFF   67584        // stream buf 0            36864
#define S1_OFF   104448       // stream buf 1            36864
#define PH_OFF   141312       // [64][68] u32 (P hi)     17408
#define PL_OFF   158720       // [64][68] u32 (P lo)     17408
#define R1_OFF   176128       // [4][64] f32             1024
#define R2_OFF   177152       // [4][64] f32             1024
#define SM_TOTAL 178176
// inside stream buf: K: hi [128][36]u32 @0 (18432B), lo @18432
//                    V: hi [64][68]u32 @0 (17408B), lo @17408

__global__ __launch_bounds__(256, 1) void attn(float* __restrict__ out) {
    extern __shared__ char smem[];
    const uint32_t sbase = smem_u32(smem);

    const int tid  = threadIdx.x;
    const int lane = tid & 31;
    const int warp = tid >> 5;
    const int mi   = warp >> 2;          // 0..1  (32-row half)
    const int ni   = warp & 3;           // 0..3  (32-col slice / 64-d slice)
    const int g    = lane >> 2;          // 0..7
    const int tg   = lane & 3;           // 0..3

    // block -> (graph, q-tile) via LPT schedule
    int s = 0;
    while (s < 7 && (int)blockIdx.x >= c_sched_start[s + 1]) s++;
    const int gr   = c_sched_g[s];
    const int tile = blockIdx.x - c_sched_start[s];
    const int nk   = c_n_g[gr];
    const int koff = c_off_g[gr];
    const int q0   = koff + tile * 64;

    const uint32_t* qh32 = (const uint32_t*)(smem + QH_OFF);
    const uint32_t* ql32 = (const uint32_t*)(smem + QL_OFF);
    uint32_t* ph32 = (uint32_t*)(smem + PH_OFF);
    uint32_t* pl32 = (uint32_t*)(smem + PL_OFF);
    float* red1 = (float*)(smem + R1_OFF);
    float* red2 = (float*)(smem + R2_OFF);

    // ---- load resident Q hi/lo [64][256] bf16, padded stride 132 u32 ----
#pragma unroll
    for (int p = 0; p < 16; p++) {
        int idx = p * 256 + tid;          // 4096 cp16 total
        int comp = idx >> 11;             // 0=hi,1=lo
        int e = idx & 2047;
        int r = e >> 5, c16 = e & 31;
        const __nv_bfloat16* src = (comp ? g_ql : g_qh) + (q0 + r) * FEAT + c16 * 8;
        cp16(sbase + (comp ? QL_OFF : QH_OFF) + r * 528 + c16 * 16, src);
    }
    cp_commit();
    cp_wait<0>();
    __syncthreads();

    // accumulators
    float O[2][4][2][4];                  // [mt][dvc][p][c]
#pragma unroll
    for (int a = 0; a < 2; a++)
#pragma unroll
        for (int b = 0; b < 4; b++)
#pragma unroll
            for (int c = 0; c < 2; c++)
#pragma unroll
                for (int d = 0; d < 4; d++) O[a][b][c][d] = 0.f;
    float Mst[2][2], Lst[2][2];
#pragma unroll
    for (int a = 0; a < 2; a++)
#pragma unroll
        for (int b = 0; b < 2; b++) { Mst[a][b] = -INFINITY; Lst[a][b] = 0.f; }

    const float scale = 0.0625f;
    const int n_kt = nk >> 7;

    for (int kt = 0; kt < n_kt; kt++) {
        const int kb = koff + kt * 128;

        float cS[2][4][4];
#pragma unroll
        for (int a = 0; a < 2; a++)
#pragma unroll
            for (int b = 0; b < 4; b++)
#pragma unroll
                for (int c = 0; c < 4; c++) cS[a][b][c] = 0.f;

        // ---------- preload K chunk 0 ----------
        {
#pragma unroll
            for (int p = 0; p < 8; p++) {
                int idx = p * 256 + tid;
                int comp = idx >> 10;
                int e = idx & 1023;
                int r = e >> 3, c16 = e & 7;
                const __nv_bfloat16* src =
                    (comp ? g_kl : g_kh) + (kb + r) * FEAT + 0 * 64 + c16 * 8;
                cp16(sbase + S0_OFF + comp * 18432 + r * 144 + c16 * 16, src);
            }
            cp_commit();
        }

        // ---------- S = Q K^T over 4 d-chunks ----------
        for (int dc = 0; dc < 4; dc++) {
            __syncthreads();   // prior chunk fully consumed before buffer reuse
            if (dc < 3) {
#pragma unroll
                for (int p = 0; p < 8; p++) {
                    int idx = p * 256 + tid;
                    int comp = idx >> 10;
                    int e = idx & 1023;
                    int r = e >> 3, c16 = e & 7;
                    const __nv_bfloat16* src =
                        (comp ? g_kl : g_kh) + (kb + r) * FEAT + (dc + 1) * 64 + c16 * 8;
                    cp16(sbase + ((dc + 1) & 1 ? S1_OFF : S0_OFF) + comp * 18432 +
                             r * 144 + c16 * 16, src);
                }
                cp_commit();
                cp_wait<1>();
            } else {
                cp_wait<0>();
            }
            __syncthreads();

            const uint32_t* kh32 =
                (const uint32_t*)(smem + (dc & 1 ? S1_OFF : S0_OFF));
            const uint32_t* kl32 = kh32 + 4608;   // 18432B

#pragma unroll
            for (int st = 0; st < 4; st++) {
                const int qc = dc * 32 + st * 8 + tg;
                const int kc = st * 8 + tg;
                uint32_t aqh[2][4], aql[2][4], bkh[4][2], bkl[4][2];
#pragma unroll
                for (int mt = 0; mt < 2; mt++) {
                    const int rb = (mi * 32 + mt * 16 + g) * 132;
                    aqh[mt][0] = qh32[rb + qc];
                    aqh[mt][1] = qh32[rb + 8 * 132 + qc];
                    aqh[mt][2] = qh32[rb + qc + 4];
                    aqh[mt][3] = qh32[rb + 8 * 132 + qc + 4];
                    aql[mt][0] = ql32[rb + qc];
                    aql[mt][1] = ql32[rb + 8 * 132 + qc];
                    aql[mt][2] = ql32[rb + qc + 4];
                    aql[mt][3] = ql32[rb + 8 * 132 + qc + 4];
                }
#pragma unroll
                for (int j = 0; j < 4; j++) {
                    const int nb = (ni * 32 + j * 8 + g) * 36;
                    bkh[j][0] = kh32[nb + kc];
                    bkh[j][1] = kh32[nb + kc + 4];
                    bkl[j][0] = kl32[nb + kc];
                    bkl[j][1] = kl32[nb + kc + 4];
                }
#pragma unroll
                for (int mt = 0; mt < 2; mt++)
#pragma unroll
                    for (int j = 0; j < 4; j++) {
                        hmma(cS[mt][j], aqh[mt][0], aqh[mt][1], aqh[mt][2],
                             aqh[mt][3], bkh[j][0], bkh[j][1]);
                        hmma(cS[mt][j], aqh[mt][0], aqh[mt][1], aqh[mt][2],
                             aqh[mt][3], bkl[j][0], bkl[j][1]);
                        hmma(cS[mt][j], aql[mt][0], aql[mt][1], aql[mt][2],
                             aql[mt][3], bkh[j][0], bkh[j][1]);
                    }
            }
        }

        // ---------- start V chunk 0 load (overlaps softmax) ----------
        __syncthreads();
        {
#pragma unroll
            for (int p = 0; p < 8; p++) {
                int idx = p * 256 + tid;
                int comp = idx >> 10;
                int e = idx & 1023;
                int r = e >> 4, c16 = e & 15;
                const __nv_bfloat16* src =
                    (comp ? g_vtl : g_vth) + (0 * 64 + r) * NTOT + kb + c16 * 8;
                cp16(sbase + S0_OFF + comp * 17408 + r * 272 + c16 * 16, src);
            }
            cp_commit();
        }

        // ---------- softmax ----------
        float alpha[2][2];
#pragma unroll
        for (int mt = 0; mt < 2; mt++)
#pragma unroll
            for (int hf = 0; hf < 2; hf++) {
                float mx = -INFINITY;
#pragma unroll
                for (int j = 0; j < 4; j++) {
                    mx = fmaxf(mx, cS[mt][j][hf * 2]);
                    mx = fmaxf(mx, cS[mt][j][hf * 2 + 1]);
                }
                mx *= scale;
                mx = fmaxf(mx, __shfl_xor_sync(0xffffffffu, mx, 1));
                mx = fmaxf(mx, __shfl_xor_sync(0xffffffffu, mx, 2));
                if (tg == 0)
                    red1[ni * 64 + mi * 32 + mt * 16 + hf * 8 + g] = mx;
            }
        __syncthreads();
#pragma unroll
        for (int mt = 0; mt < 2; mt++)
#pragma unroll
            for (int hf = 0; hf < 2; hf++) {
                const int r = mi * 32 + mt * 16 + hf * 8 + g;
                float mall = fmaxf(fmaxf(red1[r], red1[64 + r]),
                                   fmaxf(red1[128 + r], red1[192 + r]));
                float mnew = fmaxf(Mst[mt][hf], mall);
                alpha[mt][hf] = __expf(Mst[mt][hf] - mnew);
                Mst[mt][hf] = mnew;
                float psum = 0.f;
#pragma unroll
                for (int j = 0; j < 4; j++) {
                    float p0 = __expf(cS[mt][j][hf * 2] * scale - mnew);
                    float p1 = __expf(cS[mt][j][hf * 2 + 1] * scale - mnew);
                    cS[mt][j][hf * 2] = p0;
                    cS[mt][j][hf * 2 + 1] = p1;
                    psum += p0 + p1;
                }
                psum += __shfl_xor_sync(0xffffffffu, psum, 1);
                psum += __shfl_xor_sync(0xffffffffu, psum, 2);
                if (tg == 0) red2[ni * 64 + r] = psum;
            }
        __syncthreads();
#pragma unroll
        for (int mt = 0; mt < 2; mt++)
#pragma unroll
            for (int hf = 0; hf < 2; hf++) {
                const int r = mi * 32 + mt * 16 + hf * 8 + g;
                float lsum = red2[r] + red2[64 + r] + red2[128 + r] + red2[192 + r];
                Lst[mt][hf] = Lst[mt][hf] * alpha[mt][hf] + lsum;
                // rescale O rows
#pragma unroll
                for (int dv = 0; dv < 4; dv++)
#pragma unroll
                    for (int pp = 0; pp < 2; pp++) {
                        O[mt][dv][pp][hf * 2]     *= alpha[mt][hf];
                        O[mt][dv][pp][hf * 2 + 1] *= alpha[mt][hf];
                    }
                // write P hi/lo
#pragma unroll
                for (int j = 0; j < 4; j++) {
                    float p0 = cS[mt][j][hf * 2];
                    float p1 = cS[mt][j][hf * 2 + 1];
                    int a = r * 68 + ni * 16 + j * 4 + tg;
                    ph32[a] = packsplit_hi(p0, p1);
                    pl32[a] = packsplit_lo(p0, p1);
                }
            }
        __syncthreads();   // P visible everywhere

        // ---------- O += P V over 4 d-chunks ----------
        for (int dvc = 0; dvc < 4; dvc++) {
            if (dvc > 0) __syncthreads();
            if (dvc < 3) {
#pragma unroll
                for (int p = 0; p < 8; p++) {
                    int idx = p * 256 + tid;
                    int comp = idx >> 10;
                    int e = idx & 1023;
                    int r = e >> 4, c16 = e & 15;
                    const __nv_bfloat16* src =
                        (comp ? g_vtl : g_vth) + ((dvc + 1) * 64 + r) * NTOT + kb + c16 * 8;
                    cp16(sbase + ((dvc + 1) & 1 ? S1_OFF : S0_OFF) + comp * 17408 +
                             r * 272 + c16 * 16, src);
                }
                cp_commit();
                cp_wait<1>();
            } else {
                cp_wait<0>();
            }
            __syncthreads();

            const uint32_t* vh32 =
                (const uint32_t*)(smem + (dvc & 1 ? S1_OFF : S0_OFF));
            const uint32_t* vl32 = vh32 + 4352;   // 17408B

#pragma unroll
            for (int st = 0; st < 8; st++) {
                const int pc = st * 8 + tg;
                uint32_t aph[2][4], apl[2][4], bvh[2][2], bvl[2][2];
#pragma unroll
                for (int mt = 0; mt < 2; mt++) {
                    const int rb = (mi * 32 + mt * 16 + g) * 68;
                    aph[mt][0] = ph32[rb + pc];
                    aph[mt][1] = ph32[rb + 8 * 68 + pc];
                    aph[mt][2] = ph32[rb + pc + 4];
                    aph[mt][3] = ph32[rb + 8 * 68 + pc + 4];
                    apl[mt][0] = pl32[rb + pc];
                    apl[mt][1] = pl32[rb + 8 * 68 + pc];
                    apl[mt][2] = pl32[rb + pc + 4];
                    apl[mt][3] = pl32[rb + 8 * 68 + pc + 4];
                }
#pragma unroll
                for (int pp = 0; pp < 2; pp++) {
                    const int nb = (ni * 16 + pp * 8 + g) * 68;
                    bvh[pp][0] = vh32[nb + pc];
                    bvh[pp][1] = vh32[nb + pc + 4];
                    bvl[pp][0] = vl32[nb + pc];
                    bvl[pp][1] = vl32[nb + pc + 4];
                }
#pragma unroll
                for (int mt = 0; mt < 2; mt++)
#pragma unroll
                    for (int pp = 0; pp < 2; pp++) {
                        hmma(O[mt][dvc][pp], aph[mt][0], aph[mt][1], aph[mt][2],
                             aph[mt][3], bvh[pp][0], bvh[pp][1]);
                        hmma(O[mt][dvc][pp], aph[mt][0], aph[mt][1], aph[mt][2],
                             aph[mt][3], bvl[pp][0], bvl[pp][1]);
                        hmma(O[mt][dvc][pp], apl[mt][0], apl[mt][1], apl[mt][2],
                             apl[mt][3], bvh[pp][0], bvh[pp][1]);
                    }
            }
        }
        __syncthreads();   // everyone done with P/V before next iter overwrites
    }

    // ---------- epilogue ----------
#pragma unroll
    for (int mt = 0; mt < 2; mt++)
#pragma unroll
        for (int hf = 0; hf < 2; hf++) {
            const float inv = 1.0f / Lst[mt][hf];
            const int row = q0 + mi * 32 + mt * 16 + hf * 8 + g;
#pragma unroll
            for (int dv = 0; dv < 4; dv++)
#pragma unroll
                for (int pp = 0; pp < 2; pp++) {
                    const int col = dv * 64 + ni * 16 + pp * 8 + tg * 2;
                    float2 o;
                    o.x = O[mt][dv][pp][hf * 2] * inv;
                    o.y = O[mt][dv][pp][hf * 2 + 1] * inv;
                    *(float2*)&out[(size_t)row * FEAT + col] = o;
                }
        }
}

// ---------------------------------------------------------------------------
extern "C" void kernel_launch(void* const* d_in, const int* in_sizes, int n_in,
                              void* d_out, int out_size) {
    const float* s    = (const float*)d_in[0];   // [12288, 256]
    const float* W    = (const float*)d_in[1];   // [256, 768]
    const float* bias = (const float*)d_in[2];   // [768]
    float* out = (float*)d_out;                  // [12288, 256]

    cudaFuncSetAttribute(attn, cudaFuncAttributeMaxDynamicSharedMemorySize,
                         SM_TOTAL);

    qkv_gemm<<<dim3(NQKV / 64, NTOT / 64), 256>>>(s, W, bias);
    attn<<<192, 256, SM_TOTAL>>>(out);
}

// round 6
// speedup vs baseline: 4.7595x; 1.2799x over previous
#include <cuda_runtime.h>
#include <cuda_bf16.h>
#include <math.h>
#include <stdint.h>

#define FEAT 256
#define NQKV 768
#define NTOT 12288

// bf16 hi/lo splits (device globals: allocation-guard safe)
__device__ __nv_bfloat16 g_qh[NTOT * FEAT];
__device__ __nv_bfloat16 g_ql[NTOT * FEAT];
__device__ __nv_bfloat16 g_kh[NTOT * FEAT];
__device__ __nv_bfloat16 g_kl[NTOT * FEAT];
__device__ __nv_bfloat16 g_vth[FEAT * NTOT];   // V transposed: [d][key]
__device__ __nv_bfloat16 g_vtl[FEAT * NTOT];
// split inputs for the QKV HMMA GEMM
__device__ __nv_bfloat16 g_sh[NTOT * FEAT];
__device__ __nv_bfloat16 g_sl[NTOT * FEAT];
__device__ __nv_bfloat16 g_wth[NQKV * FEAT];   // W transposed: [n][k]
__device__ __nv_bfloat16 g_wtl[NQKV * FEAT];

__constant__ int c_n_g[8]   = {2048, 1536, 1024, 2048, 512, 1792, 1280, 2048};
__constant__ int c_off_g[8] = {0, 2048, 3584, 4608, 6656, 7168, 8960, 10240};
// 64-row q-tiles, LPT order (desc key count)
__constant__ int c_sched_g[8]     = {0, 3, 7, 5, 1, 6, 2, 4};
__constant__ int c_sched_start[8] = {0, 32, 64, 96, 124, 148, 168, 184};

// ---------------------------------------------------------------------------
// helpers
// ---------------------------------------------------------------------------
__device__ __forceinline__ uint32_t smem_u32(const void* p) {
    uint32_t a;
    asm("{ .reg .u64 t; cvta.to.shared.u64 t, %1; cvt.u32.u64 %0, t; }"
        : "=r"(a) : "l"(p));
    return a;
}
__device__ __forceinline__ void cp16(uint32_t dst, const void* src) {
    asm volatile(
        "{ .reg .u64 g; cvta.to.global.u64 g, %1;\n\t"
        "cp.async.cg.shared.global [%0], [g], 16; }"
        ::"r"(dst), "l"(src));
}
__device__ __forceinline__ void cp_commit() {
    asm volatile("cp.async.commit_group;" ::: "memory");
}
template <int N>
__device__ __forceinline__ void cp_wait() {
    asm volatile("cp.async.wait_group %0;" ::"n"(N) : "memory");
}
__device__ __forceinline__ void hmma(float* c, uint32_t a0, uint32_t a1,
                                     uint32_t a2, uint32_t a3,
                                     uint32_t b0, uint32_t b1) {
    asm volatile(
        "mma.sync.aligned.m16n8k16.row.col.f32.bf16.bf16.f32 "
        "{%0,%1,%2,%3}, {%4,%5,%6,%7}, {%8,%9}, {%0,%1,%2,%3};"
        : "+f"(c[0]), "+f"(c[1]), "+f"(c[2]), "+f"(c[3])
        : "r"(a0), "r"(a1), "r"(a2), "r"(a3), "r"(b0), "r"(b1));
}
__device__ __forceinline__ void split2(float x, __nv_bfloat16& h, __nv_bfloat16& l) {
    h = __float2bfloat16(x);
    l = __float2bfloat16(x - __bfloat162float(h));
}
__device__ __forceinline__ uint32_t packsplit_hi(float a, float b) {
    __nv_bfloat16 ha = __float2bfloat16(a), hb = __float2bfloat16(b);
    return (uint32_t)__bfloat16_as_ushort(ha) |
           ((uint32_t)__bfloat16_as_ushort(hb) << 16);
}
__device__ __forceinline__ uint32_t packsplit_lo(float a, float b) {
    __nv_bfloat16 ha = __float2bfloat16(a), hb = __float2bfloat16(b);
    __nv_bfloat16 la = __float2bfloat16(a - __bfloat162float(ha));
    __nv_bfloat16 lb = __float2bfloat16(b - __bfloat162float(hb));
    return (uint32_t)__bfloat16_as_ushort(la) |
           ((uint32_t)__bfloat16_as_ushort(lb) << 16);
}

// ---------------------------------------------------------------------------
// Kernel 0a: split s -> g_sh/g_sl
// ---------------------------------------------------------------------------
__global__ __launch_bounds__(256) void split_s(const float* __restrict__ S) {
    int i4 = blockIdx.x * 256 + threadIdx.x;     // 786432 threads, 4 elems each
    const float4 v = *(const float4*)&S[i4 * 4];
    __nv_bfloat16 h[4], l[4];
    split2(v.x, h[0], l[0]);
    split2(v.y, h[1], l[1]);
    split2(v.z, h[2], l[2]);
    split2(v.w, h[3], l[3]);
    uint2 ph, pl;
    ph.x = (uint32_t)__bfloat16_as_ushort(h[0]) |
           ((uint32_t)__bfloat16_as_ushort(h[1]) << 16);
    ph.y = (uint32_t)__bfloat16_as_ushort(h[2]) |
           ((uint32_t)__bfloat16_as_ushort(h[3]) << 16);
    pl.x = (uint32_t)__bfloat16_as_ushort(l[0]) |
           ((uint32_t)__bfloat16_as_ushort(l[1]) << 16);
    pl.y = (uint32_t)__bfloat16_as_ushort(l[2]) |
           ((uint32_t)__bfloat16_as_ushort(l[3]) << 16);
    *(uint2*)&g_sh[i4 * 4] = ph;
    *(uint2*)&g_sl[i4 * 4] = pl;
}

// Kernel 0b: split + transpose W -> g_wth/g_wtl  ([n][k])
__global__ __launch_bounds__(256) void split_w(const float* __restrict__ W) {
    int t = blockIdx.x * 256 + threadIdx.x;      // 196608 threads
    int k = t / NQKV, n = t % NQKV;
    __nv_bfloat16 h, l;
    split2(W[t], h, l);
    g_wth[n * FEAT + k] = h;
    g_wtl[n * FEAT + k] = l;
}

// ---------------------------------------------------------------------------
// Kernel 1: QKV GEMM via split-bf16 HMMA.
// BM=128, BN=128, K=256 in 4 chunks of 64, 256 threads (8 warps: 2M x 4N),
// warp tile m64 x n32. Epilogue routes Q/K directly; V staged through SMEM
// for coalesced transposed stores.
// ---------------------------------------------------------------------------
// smem: A0 @0, A1 @36864, B0 @73728, B1 @110592 ; each buf: hi @0, lo @18432
// (tile row stride = 36 u32 = 144B). Epilogue staging reuses offsets 0/32768.
#define GM_TOTAL 147456

__global__ __launch_bounds__(256, 1) void qkv_hmma(const float* __restrict__ bias) {
    extern __shared__ char smem[];
    const uint32_t sbase = smem_u32(smem);

    const int tid  = threadIdx.x;
    const int lane = tid & 31;
    const int warp = tid >> 5;
    const int mi   = warp >> 2;          // 0..1 (64-row half)
    const int ni   = warp & 3;           // 0..3 (32-col slice)
    const int g    = lane >> 2;
    const int tg   = lane & 3;

    const int nblk = blockIdx.x;         // 0..5
    const int n0   = nblk * 128;
    const int m0   = blockIdx.y * 128;

    float cS[4][4][4];
#pragma unroll
    for (int a = 0; a < 4; a++)
#pragma unroll
        for (int b = 0; b < 4; b++)
#pragma unroll
            for (int c = 0; c < 4; c++) cS[a][b][c] = 0.f;

    // ---- preload k-chunk 0 (A and B) into buffer 0 ----
#pragma unroll
    for (int p = 0; p < 8; p++) {
        int idx = p * 256 + tid;
        int comp = idx >> 10;
        int e = idx & 1023;
        int r = e >> 3, c16 = e & 7;
        cp16(sbase + comp * 18432 + r * 144 + c16 * 16,
             (comp ? g_sl : g_sh) + (m0 + r) * FEAT + c16 * 8);
        cp16(sbase + 73728 + comp * 18432 + r * 144 + c16 * 16,
             (comp ? g_wtl : g_wth) + (n0 + r) * FEAT + c16 * 8);
    }
    cp_commit();

    for (int kc = 0; kc < 4; kc++) {
        __syncthreads();
        if (kc < 3) {
            const uint32_t buf = ((kc + 1) & 1) ? 36864u : 0u;
#pragma unroll
            for (int p = 0; p < 8; p++) {
                int idx = p * 256 + tid;
                int comp = idx >> 10;
                int e = idx & 1023;
                int r = e >> 3, c16 = e & 7;
                cp16(sbase + buf + comp * 18432 + r * 144 + c16 * 16,
                     (comp ? g_sl : g_sh) + (m0 + r) * FEAT + (kc + 1) * 64 + c16 * 8);
                cp16(sbase + 73728 + buf + comp * 18432 + r * 144 + c16 * 16,
                     (comp ? g_wtl : g_wth) + (n0 + r) * FEAT + (kc + 1) * 64 + c16 * 8);
            }
            cp_commit();
            cp_wait<1>();
        } else {
            cp_wait<0>();
        }
        __syncthreads();

        const uint32_t* ah32 = (const uint32_t*)(smem + ((kc & 1) ? 36864 : 0));
        const uint32_t* al32 = ah32 + 4608;
        const uint32_t* bh32 = (const uint32_t*)(smem + 73728 + ((kc & 1) ? 36864 : 0));
        const uint32_t* bl32 = bh32 + 4608;

#pragma unroll
        for (int st = 0; st < 4; st++) {
            const int qc = st * 8 + tg;
            uint32_t ah[4][4], al[4][4], bh[4][2], bl[4][2];
#pragma unroll
            for (int mt = 0; mt < 4; mt++) {
                const int rb = (mi * 64 + mt * 16 + g) * 36;
                ah[mt][0] = ah32[rb + qc];
                ah[mt][1] = ah32[rb + 8 * 36 + qc];
                ah[mt][2] = ah32[rb + qc + 4];
                ah[mt][3] = ah32[rb + 8 * 36 + qc + 4];
                al[mt][0] = al32[rb + qc];
                al[mt][1] = al32[rb + 8 * 36 + qc];
                al[mt][2] = al32[rb + qc + 4];
                al[mt][3] = al32[rb + 8 * 36 + qc + 4];
            }
#pragma unroll
            for (int j = 0; j < 4; j++) {
                const int nb = (ni * 32 + j * 8 + g) * 36;
                bh[j][0] = bh32[nb + qc];
                bh[j][1] = bh32[nb + qc + 4];
                bl[j][0] = bl32[nb + qc];
                bl[j][1] = bl32[nb + qc + 4];
            }
#pragma unroll
            for (int mt = 0; mt < 4; mt++)
#pragma unroll
                for (int j = 0; j < 4; j++) {
                    hmma(cS[mt][j], ah[mt][0], ah[mt][1], ah[mt][2], ah[mt][3],
                         bh[j][0], bh[j][1]);
                    hmma(cS[mt][j], ah[mt][0], ah[mt][1], ah[mt][2], ah[mt][3],
                         bl[j][0], bl[j][1]);
                    hmma(cS[mt][j], al[mt][0], al[mt][1], al[mt][2], al[mt][3],
                         bh[j][0], bh[j][1]);
                }
        }
    }

    // ---------------- epilogue ----------------
    __syncthreads();   // done with stream buffers

    if (nblk < 4) {
        // Q (nblk 0,1) or K (nblk 2,3): direct packed stores
        __nv_bfloat16* Bh = (nblk < 2) ? g_qh : g_kh;
        __nv_bfloat16* Bl = (nblk < 2) ? g_ql : g_kl;
        const int cbase0 = (nblk & 1) * 128 + ni * 32;
#pragma unroll
        for (int mt = 0; mt < 4; mt++) {
#pragma unroll
            for (int j = 0; j < 4; j++) {
                const int cc = cbase0 + j * 8 + tg * 2;
                const float b0 = bias[(nblk < 2 ? 0 : 256) + cc];
                const float b1 = bias[(nblk < 2 ? 0 : 256) + cc + 1];
#pragma unroll
                for (int p = 0; p < 2; p++) {
                    const int row = m0 + mi * 64 + mt * 16 + g + p * 8;
                    const float v0 = cS[mt][j][p * 2] + b0;
                    const float v1 = cS[mt][j][p * 2 + 1] + b1;
                    *(uint32_t*)&Bh[row * FEAT + cc] = packsplit_hi(v0, v1);
                    *(uint32_t*)&Bl[row * FEAT + cc] = packsplit_lo(v0, v1);
                }
            }
        }
    } else {
        // V: stage [n][m] bf16 hi/lo in smem, then coalesced transposed stores
        const int d0 = n0 - 512;
#pragma unroll
        for (int mt = 0; mt < 4; mt++) {
#pragma unroll
            for (int j = 0; j < 4; j++) {
                const int nn = ni * 32 + j * 8 + tg * 2;
                const float b0 = bias[512 + d0 + nn];
                const float b1 = bias[512 + d0 + nn + 1];
#pragma unroll
                for (int p = 0; p < 2; p++) {
                    const int mm = mi * 64 + mt * 16 + g + p * 8;
                    const float v0 = cS[mt][j][p * 2] + b0;
                    const float v1 = cS[mt][j][p * 2 + 1] + b1;
                    __nv_bfloat16 h0, l0, h1, l1;
                    split2(v0, h0, l0);
                    split2(v1, h1, l1);
                    *(__nv_bfloat16*)(smem + nn * 256 + mm * 2) = h0;
                    *(__nv_bfloat16*)(smem + (nn + 1) * 256 + mm * 2) = h1;
                    *(__nv_bfloat16*)(smem + 32768 + nn * 256 + mm * 2) = l0;
                    *(__nv_bfloat16*)(smem + 32768 + (nn + 1) * 256 + mm * 2) = l1;
                }
            }
        }
        __syncthreads();
#pragma unroll
        for (int rr = 0; rr < 16; rr++) {
            const int r = warp + rr * 8;
            uint2 vh = *(uint2*)(smem + r * 256 + lane * 8);
            uint2 vl = *(uint2*)(smem + 32768 + r * 256 + lane * 8);
            *(uint2*)&g_vth[(size_t)(d0 + r) * NTOT + m0 + lane * 4] = vh;
            *(uint2*)&g_vtl[(size_t)(d0 + r) * NTOT + m0 + lane * 4] = vl;
        }
    }
}

// ---------------------------------------------------------------------------
// Kernel 2: HMMA (mma.sync bf16 split) flash attention  [unchanged from R5]
// BLOCK_M=64, BLOCK_N=128, D=256, 256 threads (8 warps: 2(M) x 4(N))
// ---------------------------------------------------------------------------
#define QH_OFF   0
#define QL_OFF   33792
#define S0_OFF   67584
#define S1_OFF   104448
#define PH_OFF   141312
#define PL_OFF   158720
#define R1_OFF   176128
#define R2_OFF   177152
#define SM_TOTAL 178176

__global__ __launch_bounds__(256, 1) void attn(float* __restrict__ out) {
    extern __shared__ char smem[];
    const uint32_t sbase = smem_u32(smem);

    const int tid  = threadIdx.x;
    const int lane = tid & 31;
    const int warp = tid >> 5;
    const int mi   = warp >> 2;
    const int ni   = warp & 3;
    const int g    = lane >> 2;
    const int tg   = lane & 3;

    int s = 0;
    while (s < 7 && (int)blockIdx.x >= c_sched_start[s + 1]) s++;
    const int gr   = c_sched_g[s];
    const int tile = blockIdx.x - c_sched_start[s];
    const int nk   = c_n_g[gr];
    const int koff = c_off_g[gr];
    const int q0   = koff + tile * 64;

    const uint32_t* qh32 = (const uint32_t*)(smem + QH_OFF);
    const uint32_t* ql32 = (const uint32_t*)(smem + QL_OFF);
    uint32_t* ph32 = (uint32_t*)(smem + PH_OFF);
    uint32_t* pl32 = (uint32_t*)(smem + PL_OFF);
    float* red1 = (float*)(smem + R1_OFF);
    float* red2 = (float*)(smem + R2_OFF);

#pragma unroll
    for (int p = 0; p < 16; p++) {
        int idx = p * 256 + tid;
        int comp = idx >> 11;
        int e = idx & 2047;
        int r = e >> 5, c16 = e & 31;
        const __nv_bfloat16* src = (comp ? g_ql : g_qh) + (q0 + r) * FEAT + c16 * 8;
        cp16(sbase + (comp ? QL_OFF : QH_OFF) + r * 528 + c16 * 16, src);
    }
    cp_commit();
    cp_wait<0>();
    __syncthreads();

    float O[2][4][2][4];
#pragma unroll
    for (int a = 0; a < 2; a++)
#pragma unroll
        for (int b = 0; b < 4; b++)
#pragma unroll
            for (int c = 0; c < 2; c++)
#pragma unroll
                for (int d = 0; d < 4; d++) O[a][b][c][d] = 0.f;
    float Mst[2][2], Lst[2][2];
#pragma unroll
    for (int a = 0; a < 2; a++)
#pragma unroll
        for (int b = 0; b < 2; b++) { Mst[a][b] = -INFINITY; Lst[a][b] = 0.f; }

    const float scale = 0.0625f;
    const int n_kt = nk >> 7;

    for (int kt = 0; kt < n_kt; kt++) {
        const int kb = koff + kt * 128;

        float cS[2][4][4];
#pragma unroll
        for (int a = 0; a < 2; a++)
#pragma unroll
            for (int b = 0; b < 4; b++)
#pragma unroll
                for (int c = 0; c < 4; c++) cS[a][b][c] = 0.f;

        {
#pragma unroll
            for (int p = 0; p < 8; p++) {
                int idx = p * 256 + tid;
                int comp = idx >> 10;
                int e = idx & 1023;
                int r = e >> 3, c16 = e & 7;
                const __nv_bfloat16* src =
                    (comp ? g_kl : g_kh) + (kb + r) * FEAT + 0 * 64 + c16 * 8;
                cp16(sbase + S0_OFF + comp * 18432 + r * 144 + c16 * 16, src);
            }
            cp_commit();
        }

        for (int dc = 0; dc < 4; dc++) {
            __syncthreads();
            if (dc < 3) {
#pragma unroll
                for (int p = 0; p < 8; p++) {
                    int idx = p * 256 + tid;
                    int comp = idx >> 10;
                    int e = idx & 1023;
                    int r = e >> 3, c16 = e & 7;
                    const __nv_bfloat16* src =
                        (comp ? g_kl : g_kh) + (kb + r) * FEAT + (dc + 1) * 64 + c16 * 8;
                    cp16(sbase + ((dc + 1) & 1 ? S1_OFF : S0_OFF) + comp * 18432 +
                             r * 144 + c16 * 16, src);
                }
                cp_commit();
                cp_wait<1>();
            } else {
                cp_wait<0>();
            }
            __syncthreads();

            const uint32_t* kh32 =
                (const uint32_t*)(smem + (dc & 1 ? S1_OFF : S0_OFF));
            const uint32_t* kl32 = kh32 + 4608;

#pragma unroll
            for (int st = 0; st < 4; st++) {
                const int qc = dc * 32 + st * 8 + tg;
                const int kc = st * 8 + tg;
                uint32_t aqh[2][4], aql[2][4], bkh[4][2], bkl[4][2];
#pragma unroll
                for (int mt = 0; mt < 2; mt++) {
                    const int rb = (mi * 32 + mt * 16 + g) * 132;
                    aqh[mt][0] = qh32[rb + qc];
                    aqh[mt][1] = qh32[rb + 8 * 132 + qc];
                    aqh[mt][2] = qh32[rb + qc + 4];
                    aqh[mt][3] = qh32[rb + 8 * 132 + qc + 4];
                    aql[mt][0] = ql32[rb + qc];
                    aql[mt][1] = ql32[rb + 8 * 132 + qc];
                    aql[mt][2] = ql32[rb + qc + 4];
                    aql[mt][3] = ql32[rb + 8 * 132 + qc + 4];
                }
#pragma unroll
                for (int j = 0; j < 4; j++) {
                    const int nb = (ni * 32 + j * 8 + g) * 36;
                    bkh[j][0] = kh32[nb + kc];
                    bkh[j][1] = kh32[nb + kc + 4];
                    bkl[j][0] = kl32[nb + kc];
                    bkl[j][1] = kl32[nb + kc + 4];
                }
#pragma unroll
                for (int mt = 0; mt < 2; mt++)
#pragma unroll
                    for (int j = 0; j < 4; j++) {
                        hmma(cS[mt][j], aqh[mt][0], aqh[mt][1], aqh[mt][2],
                             aqh[mt][3], bkh[j][0], bkh[j][1]);
                        hmma(cS[mt][j], aqh[mt][0], aqh[mt][1], aqh[mt][2],
                             aqh[mt][3], bkl[j][0], bkl[j][1]);
                        hmma(cS[mt][j], aql[mt][0], aql[mt][1], aql[mt][2],
                             aql[mt][3], bkh[j][0], bkh[j][1]);
                    }
            }
        }

        __syncthreads();
        {
#pragma unroll
            for (int p = 0; p < 8; p++) {
                int idx = p * 256 + tid;
                int comp = idx >> 10;
                int e = idx & 1023;
                int r = e >> 4, c16 = e & 15;
                const __nv_bfloat16* src =
                    (comp ? g_vtl : g_vth) + (0 * 64 + r) * NTOT + kb + c16 * 8;
                cp16(sbase + S0_OFF + comp * 17408 + r * 272 + c16 * 16, src);
            }
            cp_commit();
        }

        float alpha[2][2];
#pragma unroll
        for (int mt = 0; mt < 2; mt++)
#pragma unroll
            for (int hf = 0; hf < 2; hf++) {
                float mx = -INFINITY;
#pragma unroll
                for (int j = 0; j < 4; j++) {
                    mx = fmaxf(mx, cS[mt][j][hf * 2]);
                    mx = fmaxf(mx, cS[mt][j][hf * 2 + 1]);
                }
                mx *= scale;
                mx = fmaxf(mx, __shfl_xor_sync(0xffffffffu, mx, 1));
                mx = fmaxf(mx, __shfl_xor_sync(0xffffffffu, mx, 2));
                if (tg == 0)
                    red1[ni * 64 + mi * 32 + mt * 16 + hf * 8 + g] = mx;
            }
        __syncthreads();
#pragma unroll
        for (int mt = 0; mt < 2; mt++)
#pragma unroll
            for (int hf = 0; hf < 2; hf++) {
                const int r = mi * 32 + mt * 16 + hf * 8 + g;
                float mall = fmaxf(fmaxf(red1[r], red1[64 + r]),
                                   fmaxf(red1[128 + r], red1[192 + r]));
                float mnew = fmaxf(Mst[mt][hf], mall);
                alpha[mt][hf] = __expf(Mst[mt][hf] - mnew);
                Mst[mt][hf] = mnew;
                float psum = 0.f;
#pragma unroll
                for (int j = 0; j < 4; j++) {
                    float p0 = __expf(cS[mt][j][hf * 2] * scale - mnew);
                    float p1 = __expf(cS[mt][j][hf * 2 + 1] * scale - mnew);
                    cS[mt][j][hf * 2] = p0;
                    cS[mt][j][hf * 2 + 1] = p1;
                    psum += p0 + p1;
                }
                psum += __shfl_xor_sync(0xffffffffu, psum, 1);
                psum += __shfl_xor_sync(0xffffffffu, psum, 2);
                if (tg == 0) red2[ni * 64 + r] = psum;
            }
        __syncthreads();
#pragma unroll
        for (int mt = 0; mt < 2; mt++)
#pragma unroll
            for (int hf = 0; hf < 2; hf++) {
                const int r = mi * 32 + mt * 16 + hf * 8 + g;
                float lsum = red2[r] + red2[64 + r] + red2[128 + r] + red2[192 + r];
                Lst[mt][hf] = Lst[mt][hf] * alpha[mt][hf] + lsum;
#pragma unroll
                for (int dv = 0; dv < 4; dv++)
#pragma unroll
                    for (int pp = 0; pp < 2; pp++) {
                        O[mt][dv][pp][hf * 2]     *= alpha[mt][hf];
                        O[mt][dv][pp][hf * 2 + 1] *= alpha[mt][hf];
                    }
#pragma unroll
                for (int j = 0; j < 4; j++) {
                    float p0 = cS[mt][j][hf * 2];
                    float p1 = cS[mt][j][hf * 2 + 1];
                    int a = r * 68 + ni * 16 + j * 4 + tg;
                    ph32[a] = packsplit_hi(p0, p1);
                    pl32[a] = packsplit_lo(p0, p1);
                }
            }
        __syncthreads();

        for (int dvc = 0; dvc < 4; dvc++) {
            if (dvc > 0) __syncthreads();
            if (dvc < 3) {
#pragma unroll
                for (int p = 0; p < 8; p++) {
                    int idx = p * 256 + tid;
                    int comp = idx >> 10;
                    int e = idx & 1023;
                    int r = e >> 4, c16 = e & 15;
                    const __nv_bfloat16* src =
                        (comp ? g_vtl : g_vth) + ((dvc + 1) * 64 + r) * NTOT + kb + c16 * 8;
                    cp16(sbase + ((dvc + 1) & 1 ? S1_OFF : S0_OFF) + comp * 17408 +
                             r * 272 + c16 * 16, src);
                }
                cp_commit();
                cp_wait<1>();
            } else {
                cp_wait<0>();
            }
            __syncthreads();

            const uint32_t* vh32 =
                (const uint32_t*)(smem + (dvc & 1 ? S1_OFF : S0_OFF));
            const uint32_t* vl32 = vh32 + 4352;

#pragma unroll
            for (int st = 0; st < 8; st++) {
                const int pc = st * 8 + tg;
                uint32_t aph[2][4], apl[2][4], bvh[2][2], bvl[2][2];
#pragma unroll
                for (int mt = 0; mt < 2; mt++) {
                    const int rb = (mi * 32 + mt * 16 + g) * 68;
                    aph[mt][0] = ph32[rb + pc];
                    aph[mt][1] = ph32[rb + 8 * 68 + pc];
                    aph[mt][2] = ph32[rb + pc + 4];
                    aph[mt][3] = ph32[rb + 8 * 68 + pc + 4];
                    apl[mt][0] = pl32[rb + pc];
                    apl[mt][1] = pl32[rb + 8 * 68 + pc];
                    apl[mt][2] = pl32[rb + pc + 4];
                    apl[mt][3] = pl32[rb + 8 * 68 + pc + 4];
                }
#pragma unroll
                for (int pp = 0; pp < 2; pp++) {
                    const int nb = (ni * 16 + pp * 8 + g) * 68;
                    bvh[pp][0] = vh32[nb + pc];
                    bvh[pp][1] = vh32[nb + pc + 4];
                    bvl[pp][0] = vl32[nb + pc];
                    bvl[pp][1] = vl32[nb + pc + 4];
                }
#pragma unroll
                for (int mt = 0; mt < 2; mt++)
#pragma unroll
                    for (int pp = 0; pp < 2; pp++) {
                        hmma(O[mt][dvc][pp], aph[mt][0], aph[mt][1], aph[mt][2],
                             aph[mt][3], bvh[pp][0], bvh[pp][1]);
                        hmma(O[mt][dvc][pp], aph[mt][0], aph[mt][1], aph[mt][2],
                             aph[mt][3], bvl[pp][0], bvl[pp][1]);
                        hmma(O[mt][dvc][pp], apl[mt][0], apl[mt][1], apl[mt][2],
                             apl[mt][3], bvh[pp][0], bvh[pp][1]);
                    }
            }
        }
        __syncthreads();
    }

#pragma unroll
    for (int mt = 0; mt < 2; mt++)
#pragma unroll
        for (int hf = 0; hf < 2; hf++) {
            const float inv = 1.0f / Lst[mt][hf];
            const int row = q0 + mi * 32 + mt * 16 + hf * 8 + g;
#pragma unroll
            for (int dv = 0; dv < 4; dv++)
#pragma unroll
                for (int pp = 0; pp < 2; pp++) {
                    const int col = dv * 64 + ni * 16 + pp * 8 + tg * 2;
                    float2 o;
                    o.x = O[mt][dv][pp][hf * 2] * inv;
                    o.y = O[mt][dv][pp][hf * 2 + 1] * inv;
                    *(float2*)&out[(size_t)row * FEAT + col] = o;
                }
        }
}

// ---------------------------------------------------------------------------
extern "C" void kernel_launch(void* const* d_in, const int* in_sizes, int n_in,
                              void* d_out, int out_size) {
    const float* s    = (const float*)d_in[0];   // [12288, 256]
    const float* W    = (const float*)d_in[1];   // [256, 768]
    const float* bias = (const float*)d_in[2];   // [768]
    float* out = (float*)d_out;                  // [12288, 256]

    cudaFuncSetAttribute(qkv_hmma, cudaFuncAttributeMaxDynamicSharedMemorySize,
                         GM_TOTAL);
    cudaFuncSetAttribute(attn, cudaFuncAttributeMaxDynamicSharedMemorySize,
                         SM_TOTAL);

    split_s<<<3072, 256>>>(s);
    split_w<<<768, 256>>>(W);
    qkv_hmma<<<dim3(6, 96), 256, GM_TOTAL>>>(bias);
    attn<<<192, 256, SM_TOTAL>>>(out);
}